// round 12
// baseline (speedup 1.0000x reference)
#include <cuda_runtime.h>
#include <math.h>

#define NN 20000
#define NP 20096          // 157 * 128 (padded rows for GEMM outputs)
#define EE 320000
#define GG 128

static inline int cdiv(int a, int b) { return (a + b - 1) / b; }

// ---------------- scratch ----------------
__device__ float g_xl1[NP * 1024];
__device__ float g_xr1[NP * 1024];
__device__ float g_out1[NP * 1024];
__device__ float g_d256a[NP * 256];
__device__ float g_xr2[NP * 256];
__device__ float g_out2[NN * 256];
__device__ float g_h64[NP * 64];
__device__ float g_score[EE * 4];
__device__ float g_eacsr[EE * 8];     // edge_attr permuted to CSR order
__device__ int   g_deg[NN];
__device__ int   g_rowstart[NN + 1];
__device__ int   g_cursor[NN];
__device__ int   g_esrc[EE];
__device__ int   g_eid[EE];
__device__ float g_bnsum[1024];
__device__ float g_bnsq[1024];
__device__ float g_scale[1024];
__device__ float g_shift[1024];
__device__ float g_pool[GG * 256];
__device__ float g_fc1o[GG * 64];

// ---------------- CSR build ----------------
__global__ void hist_kernel(const int* __restrict__ ei, int* __restrict__ deg)
{
    int e = blockIdx.x * blockDim.x + threadIdx.x;
    if (e < EE) atomicAdd(&deg[ei[EE + e]], 1);
}

__global__ __launch_bounds__(512) void scan_kernel(const int* __restrict__ deg,
                                                   int* __restrict__ rowstart)
{
    __shared__ int ps[512];
    int t = threadIdx.x;
    const int CH = (NN + 511) / 512;
    int s0 = t * CH, s1 = min(NN, s0 + CH);
    int s = 0;
    for (int i = s0; i < s1; i++) s += deg[i];
    ps[t] = s;
    __syncthreads();
    for (int off = 1; off < 512; off <<= 1) {
        int v = (t >= off) ? ps[t - off] : 0;
        __syncthreads();
        ps[t] += v;
        __syncthreads();
    }
    int run = (t == 0) ? 0 : ps[t - 1];
    for (int i = s0; i < s1; i++) { rowstart[i] = run; run += deg[i]; }
    if (t == 511) rowstart[NN] = run;
}

__global__ void scatter_kernel(const int* __restrict__ ei, int* __restrict__ cursor,
                               int* __restrict__ esrc, int* __restrict__ eid)
{
    int e = blockIdx.x * blockDim.x + threadIdx.x;
    if (e >= EE) return;
    int dst = ei[EE + e];
    int pos = atomicAdd(&cursor[dst], 1);
    esrc[pos] = ei[e];
    eid[pos] = e;
}

// permute edge_attr into CSR order: ea_csr[p] = ea[eid[p]]
__global__ void permute_ea_kernel(const float* __restrict__ ea, const int* __restrict__ eid,
                                  float* __restrict__ ea_csr)
{
    int p = blockIdx.x * blockDim.x + threadIdx.x;   // one thread per (edge, pair)
    if (p >= EE * 4) return;
    int e = p >> 2;
    int q = p & 3;
    int src_e = eid[e];
    float2 v = *reinterpret_cast<const float2*>(&ea[(size_t)src_e * 8 + q * 2]);
    *reinterpret_cast<float2*>(&ea_csr[(size_t)e * 8 + q * 2]) = v;
}

// ---------------- FFMA SGEMM (R3 config): C = A[M,K] @ W[K,N] ----------------
// BM=128 BN=64 BK=16, 256 threads, TM=8 TN=4, ~80 regs, 3 CTAs/SM.
template <bool RELU, bool HAS_BIAS>
__global__ __launch_bounds__(256) void sgemm_kernel(
    const float* __restrict__ A, const float* __restrict__ W,
    const float* __restrict__ bias, float* __restrict__ C,
    int Mld, int N, int K)
{
    const int BM = 128, BN = 64, BK = 16, TM = 8, TN = 4;
    __shared__ float As[BK][BM + 1];
    __shared__ float Ws[BK][BN];
    int tid = threadIdx.x;
    int tx = tid & 15;
    int ty = tid >> 4;
    int rowBase = blockIdx.y * BM;
    int colBase = blockIdx.x * BN;

    float acc[TM][TN];
#pragma unroll
    for (int i = 0; i < TM; i++)
#pragma unroll
        for (int j = 0; j < TN; j++) acc[i][j] = 0.f;

    for (int k0 = 0; k0 < K; k0 += BK) {
#pragma unroll
        for (int l = 0; l < 8; l++) {
            int idx = tid + l * 256;
            int r = idx >> 4;
            int c = idx & 15;
            int gr = rowBase + r;
            As[c][r] = (gr < Mld) ? A[(size_t)gr * K + k0 + c] : 0.f;
        }
#pragma unroll
        for (int l = 0; l < 4; l++) {
            int idx = tid + l * 256;
            int r = idx >> 6;
            int c = idx & 63;
            Ws[r][c] = W[(size_t)(k0 + r) * N + colBase + c];
        }
        __syncthreads();
#pragma unroll
        for (int k = 0; k < BK; k++) {
            float a[TM], b[TN];
#pragma unroll
            for (int i = 0; i < TM; i++) a[i] = As[k][ty * TM + i];
            float4 bv = *reinterpret_cast<const float4*>(&Ws[k][tx * TN]);
            b[0] = bv.x; b[1] = bv.y; b[2] = bv.z; b[3] = bv.w;
#pragma unroll
            for (int i = 0; i < TM; i++)
#pragma unroll
                for (int j = 0; j < TN; j++) acc[i][j] += a[i] * b[j];
        }
        __syncthreads();
    }
#pragma unroll
    for (int i = 0; i < TM; i++) {
        int r = rowBase + ty * TM + i;
#pragma unroll
        for (int j = 0; j < TN; j++) {
            int ccol = colBase + tx * TN + j;
            float v = acc[i][j];
            if (HAS_BIAS) v += bias[ccol];
            if (RELU) v = fmaxf(v, 0.f);
            C[(size_t)r * N + ccol] = v;
        }
    }
}

// ---------------- fused GATv2 edge phase (per-dst CSR, no atomics) ----------------
// ea_csr is pre-permuted to CSR order: contiguous reads, no eid indirection.
template <int CT, int HSHIFT>
__global__ __launch_bounds__(256) void gat_edge_kernel(
    const float* __restrict__ xl, const float* __restrict__ xr,
    const float* __restrict__ ea_csr, const float* __restrict__ we,
    const float* __restrict__ att,
    const int* __restrict__ rowstart, const int* __restrict__ esrc,
    float* __restrict__ gscore_fb,
    float* __restrict__ out)
{
    constexpr int MAXDEG = 256;
    constexpr int CU = CT / 256;
    __shared__ float we_s[8 * CT];
    __shared__ float att_s[CT];
    __shared__ float xr_s[CT];
    __shared__ float sc_s[MAXDEG * 4];
    int tid = threadIdx.x, lane = tid & 31, wid = tid >> 5;
    for (int i = tid; i < 8 * CT; i += 256) we_s[i] = we[i];
    for (int i = tid; i < CT; i += 256) att_s[i] = att[i];
    __syncthreads();

    for (int node = blockIdx.x; node < NN; node += gridDim.x) {
        int rs = rowstart[node];
        int deg = rowstart[node + 1] - rs;
        if (deg == 0) {
#pragma unroll
            for (int u = 0; u < CU; u++) out[(size_t)node * CT + u * 256 + tid] = 0.f;
            continue;
        }
#pragma unroll
        for (int u = 0; u < CU; u++)
            xr_s[u * 256 + tid] = xr[(size_t)node * CT + u * 256 + tid];
        __syncthreads();
        float* sc = (deg <= MAXDEG) ? sc_s : (gscore_fb + (size_t)rs * 4);

        // pass 1: raw scores, warp per edge (ea_csr contiguous)
        for (int j = wid; j < deg; j += 8) {
            int src = esrc[rs + j];
            float eav[8];
#pragma unroll
            for (int k = 0; k < 8; k++) eav[k] = __ldg(&ea_csr[(size_t)(rs + j) * 8 + k]);
            const float* xls = xl + (size_t)src * CT;
            float acc[4] = {0.f, 0.f, 0.f, 0.f};
#pragma unroll
            for (int it = 0; it < CT / 32; it++) {
                int c = lane + 32 * it;
                const int h = (32 * it) >> HSHIFT;
                float eec = 0.f;
#pragma unroll
                for (int k = 0; k < 8; k++) eec = fmaf(eav[k], we_s[k * CT + c], eec);
                float m = xls[c] + xr_s[c] + eec;
                m = (m > 0.f) ? m : 0.2f * m;
                acc[h] = fmaf(m, att_s[c], acc[h]);
            }
#pragma unroll
            for (int h = 0; h < 4; h++) {
#pragma unroll
                for (int off = 16; off > 0; off >>= 1)
                    acc[h] += __shfl_xor_sync(0xffffffffu, acc[h], off);
            }
            if (lane == 0) {
                sc[j * 4 + 0] = acc[0];
                sc[j * 4 + 1] = acc[1];
                sc[j * 4 + 2] = acc[2];
                sc[j * 4 + 3] = acc[3];
            }
        }
        __syncthreads();

        // softmax: warps 0..3, one head each
        if (wid < 4) {
            float mx = -1e30f;
            for (int j = lane; j < deg; j += 32) mx = fmaxf(mx, sc[j * 4 + wid]);
#pragma unroll
            for (int off = 16; off > 0; off >>= 1)
                mx = fmaxf(mx, __shfl_xor_sync(0xffffffffu, mx, off));
            float sum = 0.f;
            for (int j = lane; j < deg; j += 32) {
                float v = expf(sc[j * 4 + wid] - mx);
                sc[j * 4 + wid] = v;
                sum += v;
            }
#pragma unroll
            for (int off = 16; off > 0; off >>= 1)
                sum += __shfl_xor_sync(0xffffffffu, sum, off);
            float inv = 1.f / sum;
            for (int j = lane; j < deg; j += 32) sc[j * 4 + wid] *= inv;
        }
        __syncthreads();

        // pass 2: edge-sequential, channel-parallel, unrolled x2 for MLP
        float racc[CU];
#pragma unroll
        for (int u = 0; u < CU; u++) racc[u] = 0.f;
        int j = 0;
        for (; j + 1 < deg; j += 2) {
            int s0 = esrc[rs + j];
            int s1 = esrc[rs + j + 1];
            const float* x0 = xl + (size_t)s0 * CT;
            const float* x1 = xl + (size_t)s1 * CT;
#pragma unroll
            for (int u = 0; u < CU; u++) {
                int c = u * 256 + tid;
                int h = c >> HSHIFT;
                float a0 = sc[j * 4 + h];
                float a1 = sc[(j + 1) * 4 + h];
                racc[u] = fmaf(a0, x0[c], racc[u]);
                racc[u] = fmaf(a1, x1[c], racc[u]);
            }
        }
        if (j < deg) {
            int s0 = esrc[rs + j];
            const float* x0 = xl + (size_t)s0 * CT;
#pragma unroll
            for (int u = 0; u < CU; u++) {
                int c = u * 256 + tid;
                racc[u] = fmaf(sc[j * 4 + (c >> HSHIFT)], x0[c], racc[u]);
            }
        }
#pragma unroll
        for (int u = 0; u < CU; u++)
            out[(size_t)node * CT + u * 256 + tid] = racc[u];
        __syncthreads();
    }
}

// ---------------- BN (fused bias + relu) ----------------
template <int C>
__global__ void bn_stats_kernel(const float* __restrict__ h,
                                const float* __restrict__ bias,
                                float* __restrict__ sum, float* __restrict__ sq)
{
    int c = blockIdx.y * blockDim.x + threadIdx.x;
    int r0 = blockIdx.x * 128;
    int r1 = min(NN, r0 + 128);
    float b = bias[c];
    float s = 0.f, q = 0.f;
    for (int r = r0; r < r1; r++) {
        float v = h[(size_t)r * C + c] + b;
        v = fmaxf(v, 0.f);
        s += v;
        q += v * v;
    }
    atomicAdd(&sum[c], s);
    atomicAdd(&sq[c], q);
}

__global__ void bn_final_kernel(const float* __restrict__ sum, const float* __restrict__ sq,
                                const float* __restrict__ g, const float* __restrict__ b,
                                float* __restrict__ scale, float* __restrict__ shift, int C)
{
    int c = blockIdx.x * blockDim.x + threadIdx.x;
    if (c >= C) return;
    const float invN = 1.f / (float)NN;
    float mu = sum[c] * invN;
    float var = sq[c] * invN - mu * mu;
    var = fmaxf(var, 0.f);
    float rs = rsqrtf(var + 1e-5f);
    float sc = g[c] * rs;
    scale[c] = sc;
    shift[c] = b[c] - mu * sc;
}

template <int C>
__global__ void bn_apply_kernel(float* __restrict__ h, const float* __restrict__ bias,
                                const float* __restrict__ scale, const float* __restrict__ shift)
{
    size_t i4 = (size_t)blockIdx.x * blockDim.x + threadIdx.x;
    size_t total4 = (size_t)NN * C / 4;
    if (i4 >= total4) return;
    int c = (int)((i4 * 4) % C);
    float4 v = *reinterpret_cast<float4*>(&h[i4 * 4]);
    float4 bi = *reinterpret_cast<const float4*>(&bias[c]);
    float4 sc = *reinterpret_cast<const float4*>(&scale[c]);
    float4 sh = *reinterpret_cast<const float4*>(&shift[c]);
    v.x = fmaxf(v.x + bi.x, 0.f) * sc.x + sh.x;
    v.y = fmaxf(v.y + bi.y, 0.f) * sc.y + sh.y;
    v.z = fmaxf(v.z + bi.z, 0.f) * sc.z + sh.z;
    v.w = fmaxf(v.w + bi.w, 0.f) * sc.w + sh.w;
    *reinterpret_cast<float4*>(&h[i4 * 4]) = v;
}

// ---------------- pooling (batch sorted: run-length accumulate) ------------
__global__ __launch_bounds__(256) void pool_kernel(const float* __restrict__ h,
                                                   const int* __restrict__ batch,
                                                   float* __restrict__ pooled)
{
    int c = threadIdx.x;
    int n0 = blockIdx.x * 128, n1 = min(NN, n0 + 128);
    if (n0 >= NN) return;
    float acc = 0.f;
    int cur = batch[n0];
    for (int n = n0; n < n1; n++) {
        int b = batch[n];
        if (b != cur) {
            atomicAdd(&pooled[cur * 256 + c], acc);
            acc = 0.f;
            cur = b;
        }
        acc += h[(size_t)n * 256 + c];
    }
    atomicAdd(&pooled[cur * 256 + c], acc);
}

__global__ void fc1_kernel(const float* __restrict__ pooled, const float* __restrict__ w,
                           const float* __restrict__ b, float* __restrict__ out)
{
    int gph = blockIdx.x;
    int j = threadIdx.x;
    float s = b[j];
    const float* p = pooled + gph * 256;
#pragma unroll 8
    for (int k = 0; k < 256; k++) s += p[k] * w[k * 64 + j];
    out[gph * 64 + j] = fmaxf(s, 0.f);
}

__global__ void fc2_kernel(const float* __restrict__ fc1o, const float* __restrict__ w,
                           const float* __restrict__ b, float* __restrict__ out)
{
    int gph = blockIdx.x * blockDim.x + threadIdx.x;
    if (gph >= GG) return;
    float s = b[0];
    const float* f = fc1o + gph * 64;
#pragma unroll
    for (int j = 0; j < 64; j++) s += f[j] * w[j];
    out[gph] = s;
}

// ---------------- launch ----------------
extern "C" void kernel_launch(void* const* d_in, const int* in_sizes, int n_in,
                              void* d_out, int out_size)
{
    const float* x = (const float*)d_in[0];
    const float* edge_attr = (const float*)d_in[1];
    const int* edge_index;
    const int* batch;
    int wi;
    if (in_sizes[2] == 2 * EE) {
        edge_index = (const int*)d_in[2];
        batch = (const int*)d_in[3];
        wi = 4;
    } else {
        edge_index = (const int*)d_in[n_in - 2];
        batch = (const int*)d_in[n_in - 1];
        wi = 2;
    }
    const float* dr1_w = (const float*)d_in[wi + 0];
    const float* dr1_b = (const float*)d_in[wi + 1];
    const float* dr2_w = (const float*)d_in[wi + 2];
    const float* dr2_b = (const float*)d_in[wi + 3];
    const float* c1_wl = (const float*)d_in[wi + 4];
    const float* c1_wr = (const float*)d_in[wi + 5];
    const float* c1_we = (const float*)d_in[wi + 6];
    const float* c1_att = (const float*)d_in[wi + 7];
    const float* c1_b = (const float*)d_in[wi + 8];
    const float* bn1_g = (const float*)d_in[wi + 9];
    const float* bn1_b = (const float*)d_in[wi + 10];
    const float* c2_wl = (const float*)d_in[wi + 11];
    const float* c2_wr = (const float*)d_in[wi + 12];
    const float* c2_we = (const float*)d_in[wi + 13];
    const float* c2_att = (const float*)d_in[wi + 14];
    const float* c2_b = (const float*)d_in[wi + 15];
    const float* bn2_g = (const float*)d_in[wi + 16];
    const float* bn2_b = (const float*)d_in[wi + 17];
    const float* fc1_w = (const float*)d_in[wi + 18];
    const float* fc1_b = (const float*)d_in[wi + 19];
    const float* fc2_w = (const float*)d_in[wi + 20];
    const float* fc2_b = (const float*)d_in[wi + 21];
    float* out = (float*)d_out;

    float *xl1, *xr1, *out1, *d256a, *xr2, *out2, *h64, *score, *eacsr;
    float *bnsum, *bnsq, *scalep, *shiftp, *pool, *fc1o;
    int *deg, *rowstart, *cursor, *esrc, *eid;
    cudaGetSymbolAddress((void**)&xl1, g_xl1);
    cudaGetSymbolAddress((void**)&xr1, g_xr1);
    cudaGetSymbolAddress((void**)&out1, g_out1);
    cudaGetSymbolAddress((void**)&d256a, g_d256a);
    cudaGetSymbolAddress((void**)&xr2, g_xr2);
    cudaGetSymbolAddress((void**)&out2, g_out2);
    cudaGetSymbolAddress((void**)&h64, g_h64);
    cudaGetSymbolAddress((void**)&score, g_score);
    cudaGetSymbolAddress((void**)&eacsr, g_eacsr);
    cudaGetSymbolAddress((void**)&deg, g_deg);
    cudaGetSymbolAddress((void**)&rowstart, g_rowstart);
    cudaGetSymbolAddress((void**)&cursor, g_cursor);
    cudaGetSymbolAddress((void**)&esrc, g_esrc);
    cudaGetSymbolAddress((void**)&eid, g_eid);
    cudaGetSymbolAddress((void**)&bnsum, g_bnsum);
    cudaGetSymbolAddress((void**)&bnsq, g_bnsq);
    cudaGetSymbolAddress((void**)&scalep, g_scale);
    cudaGetSymbolAddress((void**)&shiftp, g_shift);
    cudaGetSymbolAddress((void**)&pool, g_pool);
    cudaGetSymbolAddress((void**)&fc1o, g_fc1o);

    dim3 blk256(256);
    const int GY = NP / 128;   // 157

    // CSR build (dst-sorted) + edge_attr permute
    cudaMemsetAsync(deg, 0, NN * sizeof(int), 0);
    hist_kernel<<<cdiv(EE, 256), blk256>>>(edge_index, deg);
    scan_kernel<<<1, 512>>>(deg, rowstart);
    cudaMemcpyAsync(cursor, rowstart, NN * sizeof(int), cudaMemcpyDeviceToDevice, 0);
    scatter_kernel<<<cdiv(EE, 256), blk256>>>(edge_index, cursor, esrc, eid);
    permute_ea_kernel<<<cdiv(EE * 4, 256), blk256>>>(edge_attr, eid, eacsr);

    // node MLP (FFMA, R3-measured config)
    sgemm_kernel<true, true><<<dim3(4, GY), blk256>>>(
        x, dr1_w, dr1_b, d256a, NN, 256, 512);
    sgemm_kernel<false, true><<<dim3(1, GY), blk256>>>(
        d256a, dr2_w, dr2_b, h64, NP, 64, 256);
    sgemm_kernel<false, false><<<dim3(16, GY), blk256>>>(
        h64, c1_wl, nullptr, xl1, NP, 1024, 64);
    sgemm_kernel<false, false><<<dim3(16, GY), blk256>>>(
        h64, c1_wr, nullptr, xr1, NP, 1024, 64);

    // conv1 edge phase
    gat_edge_kernel<1024, 8><<<740, blk256>>>(xl1, xr1, eacsr, c1_we, c1_att,
                                              rowstart, esrc, score, out1);

    // bn1
    cudaMemsetAsync(bnsum, 0, 1024 * sizeof(float), 0);
    cudaMemsetAsync(bnsq, 0, 1024 * sizeof(float), 0);
    bn_stats_kernel<1024><<<dim3(cdiv(NN, 128), 4), blk256>>>(out1, c1_b, bnsum, bnsq);
    bn_final_kernel<<<4, blk256>>>(bnsum, bnsq, bn1_g, bn1_b, scalep, shiftp, 1024);
    bn_apply_kernel<1024><<<cdiv(NN * 1024 / 4, 256), blk256>>>(out1, c1_b, scalep, shiftp);

    // conv2 projections
    sgemm_kernel<false, false><<<dim3(4, GY), blk256>>>(
        out1, c2_wl, nullptr, d256a, NP, 256, 1024);
    sgemm_kernel<false, false><<<dim3(4, GY), blk256>>>(
        out1, c2_wr, nullptr, xr2, NP, 256, 1024);

    // conv2 edge phase
    gat_edge_kernel<256, 6><<<1184, blk256>>>(d256a, xr2, eacsr, c2_we, c2_att,
                                              rowstart, esrc, score, out2);

    // bn2
    cudaMemsetAsync(bnsum, 0, 256 * sizeof(float), 0);
    cudaMemsetAsync(bnsq, 0, 256 * sizeof(float), 0);
    bn_stats_kernel<256><<<dim3(cdiv(NN, 128), 1), blk256>>>(out2, c2_b, bnsum, bnsq);
    bn_final_kernel<<<1, blk256>>>(bnsum, bnsq, bn2_g, bn2_b, scalep, shiftp, 256);
    bn_apply_kernel<256><<<cdiv(NN * 256 / 4, 256), blk256>>>(out2, c2_b, scalep, shiftp);

    // pool + head
    cudaMemsetAsync(pool, 0, GG * 256 * sizeof(float), 0);
    pool_kernel<<<cdiv(NN, 128), blk256>>>(out2, batch, pool);
    fc1_kernel<<<GG, 64>>>(pool, fc1_w, fc1_b, fc1o);
    fc2_kernel<<<1, 128>>>(fc1o, fc2_w, fc2_b, out);
    (void)out_size; (void)n_in; (void)in_sizes;
}